// round 14
// baseline (speedup 1.0000x reference)
#include <cuda_runtime.h>

typedef unsigned long long ull;
typedef unsigned int u32;

#define NPOS   21824
#define NP4    (NPOS / 4)          // 5456
#define BATCH  8
#define KTOP   1000
#define NCLS   80
#define FULLM  0xffffffffu
#define NBINS  32768
#define HSHIFT 10
#define BASE_BIN 0xF6000u          // 0x3D800000 >> 10  (score 0.0625)
#define CAP    2048

// Scratch (no allocation allowed -> __device__ globals)
__device__ u32    g_score[BATCH * NPOS];
__device__ float4 g_boxes[BATCH * NPOS];
__device__ float  g_kind[BATCH * NPOS];
__device__ u32    g_hist[BATCH * NBINS];   // zero-init; consumed+re-zeroed by fused

__constant__ int   c_off[5]    = {0, 16384, 20480, 21504, 21760};
__constant__ int   c_logw[5]   = {7, 6, 5, 4, 3};
__constant__ float c_stride[5] = {8.f, 16.f, 32.f, 64.f, 128.f};

struct Ptrs { const float* cls[5]; const float* reg[5]; };

// ---------------------------------------------------------------------------
// Kernel 1: decode -> (score bits, box, kind) + global fine score histogram
// ---------------------------------------------------------------------------
__global__ void decode_kernel(Ptrs p) {
    int gid = blockIdx.x * blockDim.x + threadIdx.x;
    if (gid >= BATCH * NPOS) return;
    int b   = gid / NPOS;
    int pos = gid - b * NPOS;

    int lev = 0;
    if      (pos >= c_off[4]) lev = 4;
    else if (pos >= c_off[3]) lev = 3;
    else if (pos >= c_off[2]) lev = 2;
    else if (pos >= c_off[1]) lev = 1;

    int local = pos - c_off[lev];
    int lw = c_logw[lev];
    int w  = 1 << lw;
    int hw = w * w;
    int y  = local >> lw;
    int x  = local & (w - 1);

    const float* __restrict__ cbase = p.cls[lev] + (size_t)b * NCLS * hw + local;
    float best = cbase[0];
    int   bi   = 0;
    #pragma unroll 16
    for (int c = 1; c < NCLS; c++) {
        float v = cbase[(size_t)c * hw];
        if (v > best) { best = v; bi = c; }
    }
    float score = (best > 0.05f) ? best : 0.0f;

    const float* __restrict__ rbase = p.reg[lev] + (size_t)b * 4 * hw + local;
    float s  = c_stride[lev];
    float r0 = rbase[0]      * s;
    float r1 = rbase[hw]     * s;
    float r2 = rbase[2 * hw] * s;
    float r3 = rbase[3 * hw] * s;
    float cx = ((float)x + 0.5f) * s;
    float cy = ((float)y + 0.5f) * s;

    g_boxes[gid] = make_float4(cx - r0, cy - r1, cx + r2, cy + r3);
    g_kind[gid]  = (float)bi;
    u32 sb = __float_as_uint(score);
    g_score[gid] = sb;

    int idx = (int)(sb >> HSHIFT) - (int)BASE_BIN;
    idx = idx < 0 ? 0 : (idx > NBINS - 1 ? NBINS - 1 : idx);
    atomicAdd(&g_hist[b * NBINS + idx], 1u);
}

// ---------------------------------------------------------------------------
// Kernel 2 (FUSED): per-image block.
//   suffix-scan 32768-bin global hist (winner thread walks its 32 bins; hist
//   re-zeroed) -> binfloor threshold -> single collect scan ->
//   1024-key 1-thread bitonic sort (main; candcnt<=1024) /
//   2048-key 2-thread sort (<=2048) / exact radix fallback ->
//   class-bucketed sparse NMS -> sparsity-aware sweep -> output.
// key = (score_bits << 32) | (0xFFFFFFFF - pos)  reproduces jax tie-break.
// ---------------------------------------------------------------------------
#define DYN_MASK   0          // u32[1024*32] 131072 (also fallback wh scratch)
#define DYN_K2     131072     // ull[2048]  buf0  16384
#define DYN_K2B    147456     // ull[2048]  buf1  16384
#define DYN_X1     163840
#define DYN_Y1     167936
#define DYN_X2     172032
#define DYN_Y2     176128
#define DYN_AREA   180224
#define DYN_KIND   184320
#define DYN_LIST   188416
#define DYN_TOTAL  192512

__global__ void __launch_bounds__(1024, 1) fused_kernel(float* __restrict__ out) {
    extern __shared__ char smc[];
    u32*   s_mask   = (u32*)  (smc + DYN_MASK);
    ull*   s_k2     = (ull*)  (smc + DYN_K2);
    ull*   s_k2b    = (ull*)  (smc + DYN_K2B);
    float* s_x1     = (float*)(smc + DYN_X1);
    float* s_y1     = (float*)(smc + DYN_Y1);
    float* s_x2     = (float*)(smc + DYN_X2);
    float* s_y2     = (float*)(smc + DYN_Y2);
    float* s_area   = (float*)(smc + DYN_AREA);
    int*   s_kindi  = (int*)  (smc + DYN_KIND);
    u32*   s_list   = (u32*)  (smc + DYN_LIST);

    __shared__ u32 s_h256[256];
    __shared__ u32 s_warp[32];
    __shared__ int s_cnt, s_digit, s_rem;
    __shared__ u32 s_ccnt[96], s_coff[96], s_cwr[96];
    __shared__ u32 s_rowany[1024];
    __shared__ u32 s_remw[32], s_diagany[32];

    int tid  = threadIdx.x;
    int lane = tid & 31;
    int wid  = tid >> 5;
    int b    = blockIdx.x;
    const u32* __restrict__ gs = g_score + (size_t)b * NPOS;

    // ---- init ----
    s_rowany[tid] = 0;
    s_k2[tid] = 0; s_k2[tid + 1024] = 0;      // sort padding
    if (tid < 96) s_ccnt[tid] = 0;
    if (tid < 32) s_diagany[tid] = 0;

    // ---- hist: thread owns 32 contiguous bins [tid*32, tid*32+32) ----
    uint4* gh4 = (uint4*)(g_hist + (size_t)b * NBINS);
    u32 tot = 0;
    #pragma unroll
    for (int i = 0; i < 8; i++) {
        uint4 v = gh4[tid * 8 + i];
        tot += v.x + v.y + v.z + v.w;
    }
    // block suffix-scan of per-thread totals (descending-bin suffix)
    {
        u32 x = tot;
        #pragma unroll
        for (int off = 1; off < 32; off <<= 1) {
            u32 y = __shfl_down_sync(FULLM, x, off);
            if (lane + off < 32) x += y;
        }
        u32 lanes_above = x - tot;                // lanes > me in this warp
        u32 wtot = __shfl_sync(FULLM, x, 0);      // warp total
        if (lane == 0) s_warp[wid] = wtot;
        __syncthreads();
        if (tid < 32) {
            u32 wv = s_warp[lane];
            u32 xx = wv;
            #pragma unroll
            for (int off = 1; off < 32; off <<= 1) {
                u32 y = __shfl_down_sync(FULLM, xx, off);
                if (lane + off < 32) xx += y;
            }
            s_warp[lane] = xx - wv;               // warps above me
        }
        __syncthreads();
        u32 over = s_warp[wid] + lanes_above;     // count in bins above mine
        if (over < (u32)KTOP && over + tot >= (u32)KTOP) {
            // unique winner: walk own 32 bins from the top
            u32 run = over;
            int bin = -1;
            for (int i = 7; i >= 0 && bin < 0; i--) {
                uint4 v = gh4[tid * 8 + i];
                u32 arr[4] = {v.x, v.y, v.z, v.w};
                for (int e = 3; e >= 0; e--) {
                    if (bin < 0) {
                        run += arr[e];
                        if (run >= (u32)KTOP) bin = tid * 32 + i * 4 + e;
                    }
                }
            }
            s_digit = bin;
            s_rem   = (int)run;
        }
    }
    __syncthreads();
    // re-zero hist for next graph replay
    #pragma unroll
    for (int i = 0; i < 8; i++) gh4[tid * 8 + i] = make_uint4(0, 0, 0, 0);

    int bin     = s_digit;
    int candcnt = s_rem;

    if (tid == 0) s_cnt = 0;
    __syncthreads();

    if (candcnt <= CAP) {
        // ---- main path: single scan, collect all sc >= binfloor ----
        u32 thr = ((u32)(BASE_BIN + (u32)bin)) << HSHIFT;
        const uint4* __restrict__ g4 = (const uint4*)gs;
        for (int i = tid; i < NP4; i += 1024) {
            uint4 v = g4[i];
            u32 scs[4] = {v.x, v.y, v.z, v.w};
            #pragma unroll
            for (int e = 0; e < 4; e++) {
                u32 sc = scs[e];
                if (sc >= thr) {
                    int pos = i * 4 + e;
                    ull k = (((ull)sc) << 32) | (ull)(0xFFFFFFFFu - (u32)pos);
                    u32 act    = __activemask();
                    int rank   = __popc(act & ((1u << lane) - 1u));
                    int leader = __ffs(act) - 1;
                    int base   = 0;
                    if (lane == leader) base = atomicAdd(&s_cnt, __popc(act));
                    base = __shfl_sync(act, base, leader);
                    int slot = base + rank;
                    if (slot < CAP) s_k2[slot] = k;
                }
            }
        }
        __syncthreads();
    } else {
        // ---- fallback (pathological data): exact 4-pass radix select ----
        u32* whall = (u32*)(smc + DYN_MASK);        // mask region as scratch
        u32* wh    = whall + wid * 257;
        u32 prefix = 0;
        int remaining = KTOP;
        for (int shift = 24; shift >= 0; shift -= 8) {
            for (int i = tid; i < 32 * 257; i += 1024) whall[i] = 0;
            __syncthreads();
            u32 himask = (shift == 24) ? 0u : (~0u << (shift + 8));
            for (int i = tid; i < NPOS; i += 1024) {
                u32 sc = gs[i];
                if (shift == 24 || (sc & himask) == prefix) {
                    u32 d      = (sc >> shift) & 255u;
                    u32 act    = __activemask();
                    u32 peers  = __match_any_sync(act, d);
                    int leader = __ffs(peers) - 1;
                    if (lane == leader) wh[d] += (u32)__popc(peers);
                }
            }
            __syncthreads();
            if (tid < 256) {
                u32 t = 0;
                #pragma unroll
                for (int w = 0; w < 32; w++) t += whall[w * 257 + tid];
                s_h256[tid] = t;
            }
            __syncthreads();
            if (tid < 32) {
                u32 hh[8], sf[8];
                #pragma unroll
                for (int q = 0; q < 8; q++) hh[q] = s_h256[tid * 8 + q];
                u32 run = 0;
                #pragma unroll
                for (int q = 7; q >= 0; q--) { run += hh[q]; sf[q] = run; }
                u32 x = run;
                #pragma unroll
                for (int off = 1; off < 32; off <<= 1) {
                    u32 y = __shfl_down_sync(FULLM, x, off);
                    if (lane + off < 32) x += y;
                }
                u32 excl = x - run;
                #pragma unroll
                for (int q = 0; q < 8; q++) s_h256[tid * 8 + q] = sf[q] + excl;
            }
            __syncthreads();
            if (tid < 256) {
                u32 sfv  = s_h256[tid];
                u32 sfn  = (tid == 255) ? 0u : s_h256[tid + 1];
                if (sfv >= (u32)remaining && sfn < (u32)remaining) {
                    s_digit = tid;
                    s_rem   = remaining - (int)sfn;
                }
            }
            __syncthreads();
            prefix |= ((u32)s_digit) << shift;
            remaining = s_rem;
        }
        for (int i = tid; i < NPOS; i += 1024) {
            u32 sc = gs[i];
            if (sc >= prefix) {
                ull k = (((ull)sc) << 32) | (ull)(0xFFFFFFFFu - (u32)i);
                u32 act    = __activemask();
                int rank   = __popc(act & ((1u << lane) - 1u));
                int leader = __ffs(act) - 1;
                int base   = 0;
                if (lane == leader) base = atomicAdd(&s_cnt, __popc(act));
                base = __shfl_sync(act, base, leader);
                int slot = base + rank;
                if (slot < 1024) s_k2[slot] = k;
            }
        }
        __syncthreads();
        candcnt = 1024;   // force 1024-sort path below
    }

    // ---- zero the mask (after fallback scratch use; barriers below cover) ----
    {
        uint4* m4 = (uint4*)s_mask;
        #pragma unroll
        for (int i = 0; i < 8; i++) m4[tid + i * 1024] = make_uint4(0, 0, 0, 0);
    }

    ull myk;
    if (candcnt <= 1024) {
        // ================= 1024-key bitonic sort, 1 key/thread =================
        myk = s_k2[tid];
        #pragma unroll
        for (int k2 = 2; k2 <= 32; k2 <<= 1) {
            #pragma unroll
            for (int j = k2 >> 1; j > 0; j >>= 1) {
                ull pk = __shfl_xor_sync(FULLM, myk, j);
                bool tA = (((tid & k2) == 0) == ((tid & j) == 0));
                myk = tA ? (myk > pk ? myk : pk) : (myk < pk ? myk : pk);
            }
        }
        int parity = 0;
        for (int k2 = 64; k2 <= 1024; k2 <<= 1) {
            for (int j = k2 >> 1; j >= 32; j >>= 1) {
                ull* wb = parity ? s_k2b : s_k2;
                parity ^= 1;
                wb[tid] = myk;
                __syncthreads();
                ull pk = wb[tid ^ j];
                bool tA = (((tid & k2) == 0) == ((tid & j) == 0));
                myk = tA ? (myk > pk ? myk : pk) : (myk < pk ? myk : pk);
            }
            #pragma unroll
            for (int j = 16; j > 0; j >>= 1) {
                ull pk = __shfl_xor_sync(FULLM, myk, j);
                bool tA = (((tid & k2) == 0) == ((tid & j) == 0));
                myk = tA ? (myk > pk ? myk : pk) : (myk < pk ? myk : pk);
            }
        }
    } else {
        // ================= 2048-key bitonic sort, 2 keys/thread ================
        ull ka = s_k2[tid];
        ull kb = s_k2[tid + 1024];
        const int p1 = tid, p2 = tid + 1024;

        #pragma unroll
        for (int k2 = 2; k2 <= 32; k2 <<= 1) {
            #pragma unroll
            for (int j = k2 >> 1; j > 0; j >>= 1) {
                ull pa = __shfl_xor_sync(FULLM, ka, j);
                bool tA = (((p1 & k2) == 0) == ((p1 & j) == 0));
                ka = tA ? (ka > pa ? ka : pa) : (ka < pa ? ka : pa);
                ull pb = __shfl_xor_sync(FULLM, kb, j);
                bool tB = (((p2 & k2) == 0) == ((p2 & j) == 0));
                kb = tB ? (kb > pb ? kb : pb) : (kb < pb ? kb : pb);
            }
        }
        int parity = 1;
        for (int k2 = 64; k2 <= 2048; k2 <<= 1) {
            for (int j = k2 >> 1; j >= 32; j >>= 1) {
                if (j == 1024) {
                    ull mx = ka > kb ? ka : kb;
                    ull mn = ka < kb ? ka : kb;
                    ka = mx; kb = mn;
                } else {
                    ull* wb = parity ? s_k2b : s_k2;
                    parity ^= 1;
                    wb[tid] = ka;
                    wb[tid + 1024] = kb;
                    __syncthreads();
                    ull pa = wb[tid ^ j];
                    ull pb = wb[(tid ^ j) + 1024];
                    bool tA = (((p1 & k2) == 0) == ((p1 & j) == 0));
                    ka = tA ? (ka > pa ? ka : pa) : (ka < pa ? ka : pa);
                    bool tB = (((p2 & k2) == 0) == ((p2 & j) == 0));
                    kb = tB ? (kb > pb ? kb : pb) : (kb < pb ? kb : pb);
                }
            }
            #pragma unroll
            for (int j = 16; j > 0; j >>= 1) {
                ull pa = __shfl_xor_sync(FULLM, ka, j);
                bool tA = (((p1 & k2) == 0) == ((p1 & j) == 0));
                ka = tA ? (ka > pa ? ka : pa) : (ka < pa ? ka : pa);
                ull pb = __shfl_xor_sync(FULLM, kb, j);
                bool tB = (((p2 & k2) == 0) == ((p2 & j) == 0));
                kb = tB ? (kb > pb ? kb : pb) : (kb < pb ? kb : pb);
            }
        }
        myk = ka;
    }
    // myk = key at sorted position tid (descending), tid in [0,1024)

    // ---- gather boxes + count classes (match-dedup'd atomics) ----
    int myk_cls = -1;
    {
        u32 idx  = 0xFFFFFFFFu - (u32)(myk & 0xFFFFFFFFull);
        float4 bx = make_float4(0.f, 0.f, 0.f, 0.f);
        if (tid < KTOP) {
            bx = g_boxes[(size_t)b * NPOS + idx];
            myk_cls = (int)g_kind[(size_t)b * NPOS + idx];
            u32 act    = __activemask();
            u32 peers  = __match_any_sync(act, myk_cls);
            int leader = __ffs(peers) - 1;
            if (lane == leader) atomicAdd(&s_ccnt[myk_cls], (u32)__popc(peers));
        }
        s_x1[tid] = bx.x; s_y1[tid] = bx.y; s_x2[tid] = bx.z; s_y2[tid] = bx.w;
        s_kindi[tid] = myk_cls;
        s_area[tid] = fmaxf(bx.z - bx.x, 0.f) * fmaxf(bx.w - bx.y, 0.f);
    }
    __syncthreads();

    // ---- exclusive prefix over 80 (padded 96) class counts: warp 0 ----
    if (tid < 32) {
        int c0 = tid * 3;
        u32 a0 = s_ccnt[c0], a1 = s_ccnt[c0 + 1], a2 = s_ccnt[c0 + 2];
        u32 tot3 = a0 + a1 + a2;
        u32 x = tot3;
        #pragma unroll
        for (int off = 1; off < 32; off <<= 1) {
            u32 y = __shfl_up_sync(FULLM, x, off);
            if (lane >= off) x += y;
        }
        u32 excl = x - tot3;
        s_coff[c0]     = excl;           s_cwr[c0]     = excl;
        s_coff[c0 + 1] = excl + a0;      s_cwr[c0 + 1] = excl + a0;
        s_coff[c0 + 2] = excl + a0 + a1; s_cwr[c0 + 2] = excl + a0 + a1;
    }
    __syncthreads();

    // ---- scatter into class lists (match-dedup'd) ----
    int myrank = 0;
    if (tid < KTOP) {
        u32 act    = __activemask();
        u32 peers  = __match_any_sync(act, myk_cls);
        int leader = __ffs(peers) - 1;
        u32 prior  = (u32)__popc(peers & ((1u << lane) - 1u));
        u32 base   = 0;
        if (lane == leader) base = atomicAdd(&s_cwr[myk_cls], (u32)__popc(peers));
        base = __shfl_sync(act, base, leader);
        u32 slot = base + prior;
        myrank = (int)(slot - s_coff[myk_cls]);
        s_list[slot] = (u32)tid;
    }
    __syncthreads();

    // ---- same-class pair compare -> sparse mask bits + flags ----
    if (tid < KTOP) {
        int off = (int)s_coff[myk_cls];
        int n   = (int)s_cwr[myk_cls] - off;
        float bx1 = s_x1[tid], by1 = s_y1[tid], bx2 = s_x2[tid], by2 = s_y2[tid];
        for (int r = myrank + 1; r < n; r++) {
            int o = (int)s_list[off + r];
            float xx1 = fmaxf(bx1, s_x1[o]);
            float yy1 = fmaxf(by1, s_y1[o]);
            float xx2 = fminf(bx2, s_x2[o]);
            float yy2 = fminf(by2, s_y2[o]);
            float inter = fmaxf(xx2 - xx1, 0.f) * fmaxf(yy2 - yy1, 0.f);
            int i = min(tid, o), j = max(tid, o);
            float denom = s_area[i] + s_area[j] - inter + 1e-9f;
            if (inter > 0.5f * denom) {
                atomicOr(&s_mask[i * 32 + (j >> 5)], 1u << (j & 31));
                atomicOr(&s_rowany[i], 1u);
                if ((i >> 5) == (j >> 5)) atomicOr(&s_diagany[i >> 5], 1u);
            }
        }
    }
    __syncthreads();

    // ---- sparsity-aware serial sweep on warp 0 ----
    if (tid < 32) {
        u32 rem = 0;
        for (int c = 0; c < 32; c++) {
            u32 ra = s_rowany[c * 32 + lane];
            if (__reduce_or_sync(FULLM, ra) == 0u) continue;   // no edges in chunk
            u32 cur = __shfl_sync(FULLM, rem, c);
            if (s_diagany[c] == 0u) {
                // fast path: no intra-chunk edges; kept set = ~cur
                u32 K = ~cur;
                u32 a0 = 0, a1 = 0, a2 = 0, a3 = 0;
                #pragma unroll
                for (int k = 0; k < 32; k += 4) {
                    a0 |= s_mask[(c * 32 + k    ) * 32 + lane] & (u32)(((int)(K << (31 - k)))       >> 31);
                    a1 |= s_mask[(c * 32 + k + 1) * 32 + lane] & (u32)(((int)(K << (31 - (k + 1)))) >> 31);
                    a2 |= s_mask[(c * 32 + k + 2) * 32 + lane] & (u32)(((int)(K << (31 - (k + 2)))) >> 31);
                    a3 |= s_mask[(c * 32 + k + 3) * 32 + lane] & (u32)(((int)(K << (31 - (k + 3)))) >> 31);
                }
                rem |= (a0 | a1) | (a2 | a3);
            } else {
                // slow path (rare): serial chain, direct LDS
                u32 acc = 0;
                #pragma unroll 4
                for (int k = 0; k < 32; k++) {
                    if (!((cur >> k) & 1u)) {
                        acc |= s_mask[(c * 32 + k) * 32 + lane];
                        cur |= s_mask[(c * 32 + k) * 32 + c];
                    }
                }
                rem |= acc;
            }
        }
        s_remw[lane] = rem;
    }
    __syncthreads();

    // ---- output ----
    if (tid < KTOP) {
        bool removed = (s_remw[tid >> 5] >> (tid & 31)) & 1u;
        float sc = __uint_as_float((u32)(myk >> 32));
        float out_sc = (!removed && sc > 0.0f) ? sc : 0.0f;
        float* op = out + ((size_t)b * KTOP + tid) * 6;
        op[0] = s_x1[tid]; op[1] = s_y1[tid]; op[2] = s_x2[tid]; op[3] = s_y2[tid];
        op[4] = (float)s_kindi[tid];
        op[5] = out_sc;
    }
}

// ---------------------------------------------------------------------------
extern "C" void kernel_launch(void* const* d_in, const int* in_sizes, int n_in,
                              void* d_out, int out_size) {
    bool dict_order = (in_sizes[1] != 2621440);
    Ptrs p;
    for (int i = 0; i < 5; i++) {
        if (dict_order) {
            p.cls[i] = (const float*)d_in[3 * i];
            p.reg[i] = (const float*)d_in[3 * i + 2];
        } else {
            p.cls[i] = (const float*)d_in[i];
            p.reg[i] = (const float*)d_in[10 + i];
        }
    }

    int total = BATCH * NPOS;
    decode_kernel<<<(total + 255) / 256, 256>>>(p);

    cudaFuncSetAttribute(fused_kernel,
                         cudaFuncAttributeMaxDynamicSharedMemorySize, DYN_TOTAL);
    fused_kernel<<<BATCH, 1024, DYN_TOTAL>>>((float*)d_out);
}

// round 15
// speedup vs baseline: 1.4421x; 1.4421x over previous
#include <cuda_runtime.h>

typedef unsigned long long ull;
typedef unsigned int u32;

#define NPOS   21824
#define NP4    (NPOS / 4)          // 5456
#define BATCH  8
#define KTOP   1000
#define NCLS   80
#define FULLM  0xffffffffu
#define NBINS  8192
#define HSHIFT 12
#define BASE_BIN 0x3D800u          // 0x3D800000 >> 12  (score 0.0625)
#define CAP    2048

// Scratch (no allocation allowed -> __device__ globals)
__device__ u32    g_score[BATCH * NPOS];
__device__ float4 g_boxes[BATCH * NPOS];
__device__ float  g_kind[BATCH * NPOS];
__device__ u32    g_hist[BATCH * NBINS];   // zero-init; consumed+re-zeroed by fused

__constant__ int   c_off[5]    = {0, 16384, 20480, 21504, 21760};
__constant__ int   c_logw[5]   = {7, 6, 5, 4, 3};
__constant__ float c_stride[5] = {8.f, 16.f, 32.f, 64.f, 128.f};

struct Ptrs { const float* cls[5]; const float* reg[5]; };

// ---------------------------------------------------------------------------
// Kernel 1: decode -> (score bits, box, kind) + global score histogram
// ---------------------------------------------------------------------------
__global__ void decode_kernel(Ptrs p) {
    int gid = blockIdx.x * blockDim.x + threadIdx.x;
    if (gid >= BATCH * NPOS) return;
    int b   = gid / NPOS;
    int pos = gid - b * NPOS;

    int lev = 0;
    if      (pos >= c_off[4]) lev = 4;
    else if (pos >= c_off[3]) lev = 3;
    else if (pos >= c_off[2]) lev = 2;
    else if (pos >= c_off[1]) lev = 1;

    int local = pos - c_off[lev];
    int lw = c_logw[lev];
    int w  = 1 << lw;
    int hw = w * w;
    int y  = local >> lw;
    int x  = local & (w - 1);

    const float* __restrict__ cbase = p.cls[lev] + (size_t)b * NCLS * hw + local;
    float best = cbase[0];
    int   bi   = 0;
    #pragma unroll 16
    for (int c = 1; c < NCLS; c++) {
        float v = cbase[(size_t)c * hw];
        if (v > best) { best = v; bi = c; }
    }
    float score = (best > 0.05f) ? best : 0.0f;

    const float* __restrict__ rbase = p.reg[lev] + (size_t)b * 4 * hw + local;
    float s  = c_stride[lev];
    float r0 = rbase[0]      * s;
    float r1 = rbase[hw]     * s;
    float r2 = rbase[2 * hw] * s;
    float r3 = rbase[3 * hw] * s;
    float cx = ((float)x + 0.5f) * s;
    float cy = ((float)y + 0.5f) * s;

    g_boxes[gid] = make_float4(cx - r0, cy - r1, cx + r2, cy + r3);
    g_kind[gid]  = (float)bi;
    u32 sb = __float_as_uint(score);
    g_score[gid] = sb;

    int idx = (int)(sb >> HSHIFT) - (int)BASE_BIN;
    idx = idx < 0 ? 0 : (idx > NBINS - 1 ? NBINS - 1 : idx);
    atomicAdd(&g_hist[b * NBINS + idx], 1u);
}

// ---------------------------------------------------------------------------
// Kernel 2 (FUSED): per-image block.
//   suffix-scan 8192-bin global hist (8 bins/thread in regs; re-zeroed) ->
//   binfloor threshold -> single collect scan ->
//   compressed 32-bit-key bitonic sort (contiguous warp ownership; main path)
//   or 64-bit sort / exact-radix fallback (cold) ->
//   class-bucketed sparse NMS -> sparsity-aware sweep -> output.
// key order == (score desc, pos asc)  == jax top_k tie-break.
// ---------------------------------------------------------------------------
#define DYN_MASK   0          // u32[1024*32] 131072 (also fallback wh scratch)
#define DYN_K2     131072     // ull[2048]  buf0  16384 (u32[2048] view for 32-bit sort)
#define DYN_K2B    147456     // ull[2048]  buf1  16384
#define DYN_X1     163840
#define DYN_Y1     167936
#define DYN_X2     172032
#define DYN_Y2     176128
#define DYN_AREA   180224
#define DYN_KIND   184320
#define DYN_LIST   188416
#define DYN_TOTAL  192512

__global__ void __launch_bounds__(1024, 1) fused_kernel(float* __restrict__ out) {
    extern __shared__ char smc[];
    u32*   s_mask   = (u32*)  (smc + DYN_MASK);
    ull*   s_k2     = (ull*)  (smc + DYN_K2);
    ull*   s_k2b    = (ull*)  (smc + DYN_K2B);
    u32*   s_k32a   = (u32*)  (smc + DYN_K2);    // 32-bit views (2048 u32 each)
    u32*   s_k32b   = (u32*)  (smc + DYN_K2B);
    float* s_x1     = (float*)(smc + DYN_X1);
    float* s_y1     = (float*)(smc + DYN_Y1);
    float* s_x2     = (float*)(smc + DYN_X2);
    float* s_y2     = (float*)(smc + DYN_Y2);
    float* s_area   = (float*)(smc + DYN_AREA);
    int*   s_kindi  = (int*)  (smc + DYN_KIND);
    u32*   s_list   = (u32*)  (smc + DYN_LIST);

    __shared__ u32 s_h256[256];
    __shared__ u32 s_warp[32];
    __shared__ int s_cnt, s_digit, s_rem;
    __shared__ u32 s_ccnt[96], s_coff[96], s_cwr[96];
    __shared__ u32 s_rowany[1024];
    __shared__ u32 s_remw[32], s_diagany[32];

    int tid  = threadIdx.x;
    int lane = tid & 31;
    int wid  = tid >> 5;
    int b    = blockIdx.x;
    const u32* __restrict__ gs = g_score + (size_t)b * NPOS;

    // ---- init ----
    s_rowany[tid] = 0;
    s_k2[tid] = 0; s_k2[tid + 1024] = 0;      // zeroes both 64-bit and 32-bit views
    if (tid < 96) s_ccnt[tid] = 0;
    if (tid < 32) s_diagany[tid] = 0;

    // ---- hist: thread owns 8 contiguous bins via 2 uint4 (32B lane stride) ----
    u32 h[8];
    {
        uint4* gh4 = (uint4*)(g_hist + (size_t)b * NBINS);
        uint4 h0 = gh4[tid * 2], h1 = gh4[tid * 2 + 1];
        gh4[tid * 2]     = make_uint4(0, 0, 0, 0);   // reset for next graph replay
        gh4[tid * 2 + 1] = make_uint4(0, 0, 0, 0);
        h[0] = h0.x; h[1] = h0.y; h[2] = h0.z; h[3] = h0.w;
        h[4] = h1.x; h[5] = h1.y; h[6] = h1.z; h[7] = h1.w;
    }
    u32 suf[8];
    {
        u32 run = 0;
        #pragma unroll
        for (int q = 7; q >= 0; q--) { run += h[q]; suf[q] = run; }
        u32 x = run;
        #pragma unroll
        for (int off = 1; off < 32; off <<= 1) {
            u32 y = __shfl_down_sync(FULLM, x, off);
            if (lane + off < 32) x += y;
        }
        u32 lanes_above = x - run;
        u32 wtot = __shfl_sync(FULLM, x, 0);
        if (lane == 0) s_warp[wid] = wtot;
        __syncthreads();
        if (tid < 32) {
            u32 wv = s_warp[lane];
            u32 xx = wv;
            #pragma unroll
            for (int off = 1; off < 32; off <<= 1) {
                u32 y = __shfl_down_sync(FULLM, xx, off);
                if (lane + off < 32) xx += y;
            }
            s_warp[lane] = xx - wv;
        }
        if (tid == 0) s_cnt = 0;
        __syncthreads();
        u32 over = s_warp[wid] + lanes_above;     // count in bins above mine
        #pragma unroll
        for (int q = 0; q < 8; q++) {
            u32 S = suf[q] + over;
            if (S >= (u32)KTOP && (S - h[q]) < (u32)KTOP) {
                s_digit = tid * 8 + q;
                s_rem   = (int)S;
            }
        }
    }
    __syncthreads();
    int bin     = s_digit;
    int candcnt = s_rem;
    u32 thr     = ((u32)(BASE_BIN + (u32)bin)) << HSHIFT;
    // 32-bit compressed keys valid iff score range above thr fits 17 bits
    bool use32  = (candcnt <= CAP) && (thr >= 0x3F7E0000u);

    if (use32) {
        // ---- main path: single scan, collect compressed 32-bit keys ----
        const uint4* __restrict__ g4 = (const uint4*)gs;
        for (int i = tid; i < NP4; i += 1024) {
            uint4 v = g4[i];
            u32 scs[4] = {v.x, v.y, v.z, v.w};
            #pragma unroll
            for (int e = 0; e < 4; e++) {
                u32 sc = scs[e];
                if (sc >= thr) {
                    int pos = i * 4 + e;
                    u32 k = ((sc - thr) << 15) | (u32)(32767 - pos);
                    u32 act    = __activemask();
                    int rank   = __popc(act & ((1u << lane) - 1u));
                    int leader = __ffs(act) - 1;
                    int base   = 0;
                    if (lane == leader) base = atomicAdd(&s_cnt, __popc(act));
                    base = __shfl_sync(act, base, leader);
                    int slot = base + rank;
                    if (slot < CAP) s_k32a[slot] = k;
                }
            }
        }
        __syncthreads();
    } else if (candcnt <= CAP) {
        // ---- cold: collect 64-bit keys ----
        const uint4* __restrict__ g4 = (const uint4*)gs;
        for (int i = tid; i < NP4; i += 1024) {
            uint4 v = g4[i];
            u32 scs[4] = {v.x, v.y, v.z, v.w};
            #pragma unroll
            for (int e = 0; e < 4; e++) {
                u32 sc = scs[e];
                if (sc >= thr) {
                    int pos = i * 4 + e;
                    ull k = (((ull)sc) << 32) | (ull)(0xFFFFFFFFu - (u32)pos);
                    u32 act    = __activemask();
                    int rank   = __popc(act & ((1u << lane) - 1u));
                    int leader = __ffs(act) - 1;
                    int base   = 0;
                    if (lane == leader) base = atomicAdd(&s_cnt, __popc(act));
                    base = __shfl_sync(act, base, leader);
                    int slot = base + rank;
                    if (slot < CAP) s_k2[slot] = k;
                }
            }
        }
        __syncthreads();
    } else {
        // ---- fallback (pathological): exact 4-pass radix select, 64-bit keys ----
        u32* whall = (u32*)(smc + DYN_MASK);        // mask region as scratch
        u32* wh    = whall + wid * 257;
        u32 prefix = 0;
        int remaining = KTOP;
        for (int shift = 24; shift >= 0; shift -= 8) {
            for (int i = tid; i < 32 * 257; i += 1024) whall[i] = 0;
            __syncthreads();
            u32 himask = (shift == 24) ? 0u : (~0u << (shift + 8));
            for (int i = tid; i < NPOS; i += 1024) {
                u32 sc = gs[i];
                if (shift == 24 || (sc & himask) == prefix) {
                    u32 d      = (sc >> shift) & 255u;
                    u32 act    = __activemask();
                    u32 peers  = __match_any_sync(act, d);
                    int leader = __ffs(peers) - 1;
                    if (lane == leader) wh[d] += (u32)__popc(peers);
                }
            }
            __syncthreads();
            if (tid < 256) {
                u32 t = 0;
                #pragma unroll
                for (int w = 0; w < 32; w++) t += whall[w * 257 + tid];
                s_h256[tid] = t;
            }
            __syncthreads();
            if (tid < 32) {
                u32 hh[8], sf[8];
                #pragma unroll
                for (int q = 0; q < 8; q++) hh[q] = s_h256[tid * 8 + q];
                u32 run = 0;
                #pragma unroll
                for (int q = 7; q >= 0; q--) { run += hh[q]; sf[q] = run; }
                u32 x = run;
                #pragma unroll
                for (int off = 1; off < 32; off <<= 1) {
                    u32 y = __shfl_down_sync(FULLM, x, off);
                    if (lane + off < 32) x += y;
                }
                u32 excl = x - run;
                #pragma unroll
                for (int q = 0; q < 8; q++) s_h256[tid * 8 + q] = sf[q] + excl;
            }
            __syncthreads();
            if (tid < 256) {
                u32 sfv  = s_h256[tid];
                u32 sfn  = (tid == 255) ? 0u : s_h256[tid + 1];
                if (sfv >= (u32)remaining && sfn < (u32)remaining) {
                    s_digit = tid;
                    s_rem   = remaining - (int)sfn;
                }
            }
            __syncthreads();
            prefix |= ((u32)s_digit) << shift;
            remaining = s_rem;
        }
        for (int i = tid; i < NPOS; i += 1024) {
            u32 sc = gs[i];
            if (sc >= prefix) {
                ull k = (((ull)sc) << 32) | (ull)(0xFFFFFFFFu - (u32)i);
                u32 act    = __activemask();
                int rank   = __popc(act & ((1u << lane) - 1u));
                int leader = __ffs(act) - 1;
                int base   = 0;
                if (lane == leader) base = atomicAdd(&s_cnt, __popc(act));
                base = __shfl_sync(act, base, leader);
                int slot = base + rank;
                if (slot < CAP) s_k2[slot] = k;
            }
        }
        __syncthreads();
    }

    // ---- zero the mask (after fallback scratch use; barriers below cover) ----
    {
        uint4* m4 = (uint4*)s_mask;
        #pragma unroll
        for (int i = 0; i < 8; i++) m4[tid + i * 1024] = make_uint4(0, 0, 0, 0);
    }

    u32 my_sc, my_idx;
    if (use32) {
        // ======= 2048-key 32-bit bitonic sort, contiguous warp ownership =======
        // warp w owns positions [64w, 64w+64); thread: p1 = 64w+lane, p2 = p1+32.
        const int p1 = (wid << 6) + lane;
        const int p2 = p1 + 32;
        u32 ka = s_k32a[p1];
        u32 kb = s_k32a[p2];

        #pragma unroll
        for (int k2 = 2; k2 <= 32; k2 <<= 1) {
            #pragma unroll
            for (int j = k2 >> 1; j > 0; j >>= 1) {
                u32 pa = __shfl_xor_sync(FULLM, ka, j);
                bool tA = (((p1 & k2) == 0) == ((p1 & j) == 0));
                ka = tA ? (ka > pa ? ka : pa) : (ka < pa ? ka : pa);
                u32 pb = __shfl_xor_sync(FULLM, kb, j);
                bool tB = (((p2 & k2) == 0) == ((p2 & j) == 0));
                kb = tB ? (kb > pb ? kb : pb) : (kb < pb ? kb : pb);
            }
        }
        int parity = 0;
        for (int k2 = 64; k2 <= 2048; k2 <<= 1) {
            for (int j = k2 >> 1; j >= 64; j >>= 1) {       // cross-warp: smem
                u32* wb = parity ? s_k32b : s_k32a;
                parity ^= 1;
                wb[p1] = ka;
                wb[p2] = kb;
                __syncthreads();
                u32 pa = wb[p1 ^ j];
                u32 pb = wb[p2 ^ j];
                bool tA = (((p1 & k2) == 0) == ((p1 & j) == 0));
                ka = tA ? (ka > pa ? ka : pa) : (ka < pa ? ka : pa);
                bool tB = (((p2 & k2) == 0) == ((p2 & j) == 0));
                kb = tB ? (kb > pb ? kb : pb) : (kb < pb ? kb : pb);
            }
            {   // j = 32: in-thread (p2 = p1 ^ 32; p1 has bit5 clear)
                bool tA = ((p1 & k2) == 0);
                u32 mx = ka > kb ? ka : kb;
                u32 mn = ka < kb ? ka : kb;
                ka = tA ? mx : mn;
                kb = tA ? mn : mx;
            }
            #pragma unroll
            for (int j = 16; j > 0; j >>= 1) {              // intra-warp: shfl
                u32 pa = __shfl_xor_sync(FULLM, ka, j);
                bool tA = (((p1 & k2) == 0) == ((p1 & j) == 0));
                ka = tA ? (ka > pa ? ka : pa) : (ka < pa ? ka : pa);
                u32 pb = __shfl_xor_sync(FULLM, kb, j);
                bool tB = (((p2 & k2) == 0) == ((p2 & j) == 0));
                kb = tB ? (kb > pb ? kb : pb) : (kb < pb ? kb : pb);
            }
        }
        // gather rank tid (write to the fresh buffer -> no extra barrier)
        {
            u32* wb = parity ? s_k32b : s_k32a;
            wb[p1] = ka;
            wb[p2] = kb;
            __syncthreads();
            u32 k = wb[tid];
            my_sc  = (k >> 15) + thr;
            my_idx = 32767u - (k & 0x7FFFu);
        }
    } else {
        // ======= cold: 2048-key 64-bit bitonic sort (2 keys/thread) =======
        ull ka = s_k2[tid];
        ull kb = s_k2[tid + 1024];
        const int p1 = tid, p2 = tid + 1024;

        #pragma unroll
        for (int k2 = 2; k2 <= 32; k2 <<= 1) {
            #pragma unroll
            for (int j = k2 >> 1; j > 0; j >>= 1) {
                ull pa = __shfl_xor_sync(FULLM, ka, j);
                bool tA = (((p1 & k2) == 0) == ((p1 & j) == 0));
                ka = tA ? (ka > pa ? ka : pa) : (ka < pa ? ka : pa);
                ull pb = __shfl_xor_sync(FULLM, kb, j);
                bool tB = (((p2 & k2) == 0) == ((p2 & j) == 0));
                kb = tB ? (kb > pb ? kb : pb) : (kb < pb ? kb : pb);
            }
        }
        int parity = 1;
        for (int k2 = 64; k2 <= 2048; k2 <<= 1) {
            for (int j = k2 >> 1; j >= 32; j >>= 1) {
                if (j == 1024) {
                    ull mx = ka > kb ? ka : kb;
                    ull mn = ka < kb ? ka : kb;
                    ka = mx; kb = mn;
                } else {
                    ull* wb = parity ? s_k2b : s_k2;
                    parity ^= 1;
                    wb[tid] = ka;
                    wb[tid + 1024] = kb;
                    __syncthreads();
                    ull pa = wb[tid ^ j];
                    ull pb = wb[(tid ^ j) + 1024];
                    bool tA = (((p1 & k2) == 0) == ((p1 & j) == 0));
                    ka = tA ? (ka > pa ? ka : pa) : (ka < pa ? ka : pa);
                    bool tB = (((p2 & k2) == 0) == ((p2 & j) == 0));
                    kb = tB ? (kb > pb ? kb : pb) : (kb < pb ? kb : pb);
                }
            }
            #pragma unroll
            for (int j = 16; j > 0; j >>= 1) {
                ull pa = __shfl_xor_sync(FULLM, ka, j);
                bool tA = (((p1 & k2) == 0) == ((p1 & j) == 0));
                ka = tA ? (ka > pa ? ka : pa) : (ka < pa ? ka : pa);
                ull pb = __shfl_xor_sync(FULLM, kb, j);
                bool tB = (((p2 & k2) == 0) == ((p2 & j) == 0));
                kb = tB ? (kb > pb ? kb : pb) : (kb < pb ? kb : pb);
            }
        }
        my_sc  = (u32)(ka >> 32);
        my_idx = 0xFFFFFFFFu - (u32)(ka & 0xFFFFFFFFull);
    }
    // (my_sc, my_idx) = score bits + position at sorted rank tid (descending)

    // ---- gather boxes + count classes (match-dedup'd atomics) ----
    int myk_cls = -1;
    {
        float4 bx = make_float4(0.f, 0.f, 0.f, 0.f);
        if (tid < KTOP) {
            bx = g_boxes[(size_t)b * NPOS + my_idx];
            myk_cls = (int)g_kind[(size_t)b * NPOS + my_idx];
            u32 act    = __activemask();
            u32 peers  = __match_any_sync(act, myk_cls);
            int leader = __ffs(peers) - 1;
            if (lane == leader) atomicAdd(&s_ccnt[myk_cls], (u32)__popc(peers));
        }
        s_x1[tid] = bx.x; s_y1[tid] = bx.y; s_x2[tid] = bx.z; s_y2[tid] = bx.w;
        s_kindi[tid] = myk_cls;
        s_area[tid] = fmaxf(bx.z - bx.x, 0.f) * fmaxf(bx.w - bx.y, 0.f);
    }
    __syncthreads();

    // ---- exclusive prefix over 80 (padded 96) class counts: warp 0 ----
    if (tid < 32) {
        int c0 = tid * 3;
        u32 a0 = s_ccnt[c0], a1 = s_ccnt[c0 + 1], a2 = s_ccnt[c0 + 2];
        u32 tot3 = a0 + a1 + a2;
        u32 x = tot3;
        #pragma unroll
        for (int off = 1; off < 32; off <<= 1) {
            u32 y = __shfl_up_sync(FULLM, x, off);
            if (lane >= off) x += y;
        }
        u32 excl = x - tot3;
        s_coff[c0]     = excl;           s_cwr[c0]     = excl;
        s_coff[c0 + 1] = excl + a0;      s_cwr[c0 + 1] = excl + a0;
        s_coff[c0 + 2] = excl + a0 + a1; s_cwr[c0 + 2] = excl + a0 + a1;
    }
    __syncthreads();

    // ---- scatter into class lists (match-dedup'd) ----
    int myrank = 0;
    if (tid < KTOP) {
        u32 act    = __activemask();
        u32 peers  = __match_any_sync(act, myk_cls);
        int leader = __ffs(peers) - 1;
        u32 prior  = (u32)__popc(peers & ((1u << lane) - 1u));
        u32 base   = 0;
        if (lane == leader) base = atomicAdd(&s_cwr[myk_cls], (u32)__popc(peers));
        base = __shfl_sync(act, base, leader);
        u32 slot = base + prior;
        myrank = (int)(slot - s_coff[myk_cls]);
        s_list[slot] = (u32)tid;
    }
    __syncthreads();

    // ---- same-class pair compare -> sparse mask bits + flags ----
    if (tid < KTOP) {
        int off = (int)s_coff[myk_cls];
        int n   = (int)s_cwr[myk_cls] - off;
        float bx1 = s_x1[tid], by1 = s_y1[tid], bx2 = s_x2[tid], by2 = s_y2[tid];
        for (int r = myrank + 1; r < n; r++) {
            int o = (int)s_list[off + r];
            float xx1 = fmaxf(bx1, s_x1[o]);
            float yy1 = fmaxf(by1, s_y1[o]);
            float xx2 = fminf(bx2, s_x2[o]);
            float yy2 = fminf(by2, s_y2[o]);
            float inter = fmaxf(xx2 - xx1, 0.f) * fmaxf(yy2 - yy1, 0.f);
            int i = min(tid, o), j = max(tid, o);
            float denom = s_area[i] + s_area[j] - inter + 1e-9f;
            if (inter > 0.5f * denom) {
                atomicOr(&s_mask[i * 32 + (j >> 5)], 1u << (j & 31));
                atomicOr(&s_rowany[i], 1u);
                if ((i >> 5) == (j >> 5)) atomicOr(&s_diagany[i >> 5], 1u);
            }
        }
    }
    __syncthreads();

    // ---- sparsity-aware serial sweep on warp 0 ----
    if (tid < 32) {
        u32 rem = 0;
        for (int c = 0; c < 32; c++) {
            u32 ra = s_rowany[c * 32 + lane];
            if (__reduce_or_sync(FULLM, ra) == 0u) continue;   // no edges in chunk
            u32 cur = __shfl_sync(FULLM, rem, c);
            if (s_diagany[c] == 0u) {
                // fast path: no intra-chunk edges; kept set = ~cur
                u32 K = ~cur;
                u32 a0 = 0, a1 = 0, a2 = 0, a3 = 0;
                #pragma unroll
                for (int k = 0; k < 32; k += 4) {
                    a0 |= s_mask[(c * 32 + k    ) * 32 + lane] & (u32)(((int)(K << (31 - k)))       >> 31);
                    a1 |= s_mask[(c * 32 + k + 1) * 32 + lane] & (u32)(((int)(K << (31 - (k + 1)))) >> 31);
                    a2 |= s_mask[(c * 32 + k + 2) * 32 + lane] & (u32)(((int)(K << (31 - (k + 2)))) >> 31);
                    a3 |= s_mask[(c * 32 + k + 3) * 32 + lane] & (u32)(((int)(K << (31 - (k + 3)))) >> 31);
                }
                rem |= (a0 | a1) | (a2 | a3);
            } else {
                // slow path (rare): serial chain, direct LDS
                u32 acc = 0;
                #pragma unroll 4
                for (int k = 0; k < 32; k++) {
                    if (!((cur >> k) & 1u)) {
                        acc |= s_mask[(c * 32 + k) * 32 + lane];
                        cur |= s_mask[(c * 32 + k) * 32 + c];
                    }
                }
                rem |= acc;
            }
        }
        s_remw[lane] = rem;
    }
    __syncthreads();

    // ---- output ----
    if (tid < KTOP) {
        bool removed = (s_remw[tid >> 5] >> (tid & 31)) & 1u;
        float sc = __uint_as_float(my_sc);
        float out_sc = (!removed && sc > 0.0f) ? sc : 0.0f;
        float* op = out + ((size_t)b * KTOP + tid) * 6;
        op[0] = s_x1[tid]; op[1] = s_y1[tid]; op[2] = s_x2[tid]; op[3] = s_y2[tid];
        op[4] = (float)s_kindi[tid];
        op[5] = out_sc;
    }
}

// ---------------------------------------------------------------------------
extern "C" void kernel_launch(void* const* d_in, const int* in_sizes, int n_in,
                              void* d_out, int out_size) {
    bool dict_order = (in_sizes[1] != 2621440);
    Ptrs p;
    for (int i = 0; i < 5; i++) {
        if (dict_order) {
            p.cls[i] = (const float*)d_in[3 * i];
            p.reg[i] = (const float*)d_in[3 * i + 2];
        } else {
            p.cls[i] = (const float*)d_in[i];
            p.reg[i] = (const float*)d_in[10 + i];
        }
    }

    int total = BATCH * NPOS;
    decode_kernel<<<(total + 255) / 256, 256>>>(p);

    cudaFuncSetAttribute(fused_kernel,
                         cudaFuncAttributeMaxDynamicSharedMemorySize, DYN_TOTAL);
    fused_kernel<<<BATCH, 1024, DYN_TOTAL>>>((float*)d_out);
}